// round 11
// baseline (speedup 1.0000x reference)
#include <cuda_runtime.h>
#include <cstdint>

// Problem: B=64, T=2048, H=256, A=4.
// Identity (rel_err==0.0 across R2-R10): out[b,t,h*4+a] = (t>0) ? X[b,t,h] : 0.
// The reference's softmax-prefix weight w_avg = se_excl/se_excl (0-guarded) is
// exactly 1.0f for t>0, 0.0f at t=0, so the GEMM/tanh/softmax chain is dead code.
//
// FINAL FORM (converged): the kernel is pinned at ~6.3 TB/s aggregate
// (128 MiB read + 512 MiB write, both mandatory) — the chip-level LTS
// bytes/cycle cap (path-independent), with all SM pipes idle and perf
// insensitive to occupancy. Concurrency map: MLP_p1 1 -> 117us, 4 -> ~98us,
// 8 -> ~103us; width of loads/stores at MLP=4 is neutral. This variant:
//   - 4 front-batched independent 128-bit streaming loads (warp: 2 KB/step)
//   - 8 x 256-bit full-sector streaming stores (warp: 8 KB contiguous/body)
//   - t==0 rows: loads predicated off, zeros stored.

static constexpr int B = 64;
static constexpr int T = 2048;
static constexpr int H = 256;

static constexpr unsigned NF4 = (unsigned)B * T * H / 4;       // 8,388,608 float4
static constexpr int THREADS = 256;
static constexpr int UNROLL = 4;
static constexpr unsigned BLOCKS = NF4 / (THREADS * UNROLL);   // 8,192

__device__ __forceinline__ void stg256_cs(void* p, uint32_t lo, uint32_t hi) {
    // [splat(lo) x4 | splat(hi) x4] — 32 bytes, 32 B aligned.
    asm volatile(
        "st.global.cs.v8.b32 [%0], {%1,%1,%1,%1,%2,%2,%2,%2};"
        :: "l"(p), "r"(lo), "r"(hi)
        : "memory");
}

__global__ __launch_bounds__(THREADS)
void attn_splat_final_kernel(const float4* __restrict__ X4, char* __restrict__ out) {
    unsigned q0 = blockIdx.x * (THREADS * UNROLL) + threadIdx.x;

    // One H-row = 64 float4s, so t = (q >> 6) & 2047. Rows with t==0 emit zeros
    // and never read X (predicated-off load).
    float4 x[UNROLL];
#pragma unroll
    for (int k = 0; k < UNROLL; k++) {
        unsigned q = q0 + k * THREADS;
        if (((q >> 6) & 2047u) != 0u) {
            x[k] = __ldcs(X4 + q);
        } else {
            x[k] = make_float4(0.0f, 0.0f, 0.0f, 0.0f);
        }
    }

    // Each float4 -> 64 B of output: two v8 stores. Warp: 2 KB contiguous/step.
#pragma unroll
    for (int k = 0; k < UNROLL; k++) {
        unsigned q = q0 + k * THREADS;
        char* p = out + (size_t)q * 64u;
        stg256_cs(p,      __float_as_uint(x[k].x), __float_as_uint(x[k].y));
        stg256_cs(p + 32, __float_as_uint(x[k].z), __float_as_uint(x[k].w));
    }
}

extern "C" void kernel_launch(void* const* d_in, const int* in_sizes, int n_in,
                              void* d_out, int out_size) {
    // metadata order: X, W1, b1, W2, b2. Only X is needed (see identity above).
    const float4* X4 = (const float4*)d_in[0];
    attn_splat_final_kernel<<<BLOCKS, THREADS>>>(X4, (char*)d_out);
}

// round 12
// speedup vs baseline: 1.0060x; 1.0060x over previous
#include <cuda_runtime.h>
#include <cstdint>

// Problem: B=64, T=2048, H=256, A=4.
// Exact identity (rel_err==0.0 across R2-R11): out[b,t,h*4+a] = (t>0)?X[b,t,h]:0.
// The reference's w_avg = se_excl/se_excl (0-guarded) is exactly 1.0f for t>0,
// 0.0f at t=0 — the GEMM/tanh/softmax chain is dead code.
//
// FINAL (converged, best-measured variant = R10): pinned at ~6.3 TB/s
// aggregate HBM (128 MiB read + 512 MiB write, both mandatory) — the
// chip-level LTS bytes/cycle cap, path-independent. Perf is insensitive to
// occupancy (50% vs 78% identical), block shape, and load/store width at
// MLP_p1=4. Concurrency map: MLP_p1 1 -> 117us, 4 -> ~97.5us, 8 -> ~103us.
//   - 4 front-batched independent 128-bit streaming loads (warp: 2 KB/step)
//   - 8 x 256-bit full-sector streaming stores (warp: 8 KB contiguous/body)
//   - branchless zeroing of t==0 rows.

static constexpr int B = 64;
static constexpr int T = 2048;
static constexpr int H = 256;

static constexpr unsigned NF4 = (unsigned)B * T * H / 4;       // 8,388,608 float4
static constexpr int THREADS = 256;
static constexpr int UNROLL = 4;
static constexpr unsigned BLOCKS = NF4 / (THREADS * UNROLL);   // 8,192

__device__ __forceinline__ void stg256_cs(void* p, uint32_t lo, uint32_t hi) {
    // [splat(lo) x4 | splat(hi) x4] — 32 bytes, 32 B aligned.
    asm volatile(
        "st.global.cs.v8.b32 [%0], {%1,%1,%1,%1,%2,%2,%2,%2};"
        :: "l"(p), "r"(lo), "r"(hi)
        : "memory");
}

__global__ __launch_bounds__(THREADS)
void attn_splat_v8w_kernel(const float4* __restrict__ X4, char* __restrict__ out) {
    unsigned q0 = blockIdx.x * (THREADS * UNROLL) + threadIdx.x;

    // Front batch: 4 independent 128-bit streaming loads (MLP_p1 = 4).
    float4 x[UNROLL];
#pragma unroll
    for (int k = 0; k < UNROLL; k++)
        x[k] = __ldcs(X4 + q0 + k * THREADS);

    // float4 index q covers scalars 4q..4q+3 — one H-row holds 64 float4s,
    // so t = (q >> 6) & 2047; zero the t==0 rows (w_avg == 0 at t=0).
#pragma unroll
    for (int k = 0; k < UNROLL; k++) {
        unsigned q = q0 + k * THREADS;
        if (((q >> 6) & 2047u) == 0u) {
            x[k].x = 0.0f; x[k].y = 0.0f; x[k].z = 0.0f; x[k].w = 0.0f;
        }
    }

    // Each float4 -> 64 B of output: two v8 stores (each [splat|splat] 32 B).
    // Warp writes 2 KB contiguous per unroll step.
#pragma unroll
    for (int k = 0; k < UNROLL; k++) {
        unsigned q = q0 + k * THREADS;
        char* p = out + (size_t)q * 64u;
        stg256_cs(p,      __float_as_uint(x[k].x), __float_as_uint(x[k].y));
        stg256_cs(p + 32, __float_as_uint(x[k].z), __float_as_uint(x[k].w));
    }
}

extern "C" void kernel_launch(void* const* d_in, const int* in_sizes, int n_in,
                              void* d_out, int out_size) {
    // metadata order: X, W1, b1, W2, b2. Only X is needed (see identity above).
    const float4* X4 = (const float4*)d_in[0];
    attn_splat_v8w_kernel<<<BLOCKS, THREADS>>>(X4, (char*)d_out);
}

// round 14
// speedup vs baseline: 1.0098x; 1.0038x over previous
#include <cuda_runtime.h>
#include <cstdint>

// Problem: B=64, T=2048, H=256, A=4.
// Exact identity (rel_err==0.0 across R2-R12): out[b,t,h*4+a] = (t>0)?X[b,t,h]:0.
// The reference's w_avg = se_excl/se_excl (0-guarded) is exactly 1.0f for t>0,
// 0.0f at t=0 — the GEMM/tanh/softmax chain is dead code.
//
// FINAL (converged; best-measured: 96.5us ncu, DRAM 80.6% @ 6384 GB/s):
// pinned at the chip-level LTS bytes/cycle cap (~6300 B/cyc, path-independent)
// with the mandatory 128 MiB read + 512 MiB write footprint. Perf is
// insensitive to occupancy (50% == 78%), block shape, and load/store width at
// MLP_p1=4. Concurrency map: MLP_p1 1 -> 117us, 4 -> ~97us, 8 -> ~103us.
//   - 4 front-batched independent 128-bit streaming loads (warp: 2 KB/step)
//   - 8 x 256-bit full-sector streaming stores (warp: 8 KB contiguous/body)
//   - branchless zeroing of t==0 rows.

static constexpr int B = 64;
static constexpr int T = 2048;
static constexpr int H = 256;

static constexpr unsigned NF4 = (unsigned)B * T * H / 4;       // 8,388,608 float4
static constexpr int THREADS = 256;
static constexpr int UNROLL = 4;
static constexpr unsigned BLOCKS = NF4 / (THREADS * UNROLL);   // 8,192

__device__ __forceinline__ void stg256_cs(void* p, uint32_t lo, uint32_t hi) {
    // [splat(lo) x4 | splat(hi) x4] — 32 bytes, 32 B aligned.
    asm volatile(
        "st.global.cs.v8.b32 [%0], {%1,%1,%1,%1,%2,%2,%2,%2};"
        :: "l"(p), "r"(lo), "r"(hi)
        : "memory");
}

__global__ __launch_bounds__(THREADS)
void attn_splat_v8w_kernel(const float4* __restrict__ X4, char* __restrict__ out) {
    unsigned q0 = blockIdx.x * (THREADS * UNROLL) + threadIdx.x;

    // Front batch: 4 independent 128-bit streaming loads (MLP_p1 = 4).
    float4 x[UNROLL];
#pragma unroll
    for (int k = 0; k < UNROLL; k++)
        x[k] = __ldcs(X4 + q0 + k * THREADS);

    // float4 index q covers scalars 4q..4q+3 — one H-row holds 64 float4s,
    // so t = (q >> 6) & 2047; zero the t==0 rows (w_avg == 0 at t=0).
#pragma unroll
    for (int k = 0; k < UNROLL; k++) {
        unsigned q = q0 + k * THREADS;
        if (((q >> 6) & 2047u) == 0u) {
            x[k].x = 0.0f; x[k].y = 0.0f; x[k].z = 0.0f; x[k].w = 0.0f;
        }
    }

    // Each float4 -> 64 B of output: two v8 stores (each [splat|splat] 32 B).
    // Warp writes 2 KB contiguous per unroll step.
#pragma unroll
    for (int k = 0; k < UNROLL; k++) {
        unsigned q = q0 + k * THREADS;
        char* p = out + (size_t)q * 64u;
        stg256_cs(p,      __float_as_uint(x[k].x), __float_as_uint(x[k].y));
        stg256_cs(p + 32, __float_as_uint(x[k].z), __float_as_uint(x[k].w));
    }
}

extern "C" void kernel_launch(void* const* d_in, const int* in_sizes, int n_in,
                              void* d_out, int out_size) {
    // metadata order: X, W1, b1, W2, b2. Only X is needed (see identity above).
    const float4* X4 = (const float4*)d_in[0];
    attn_splat_v8w_kernel<<<BLOCKS, THREADS>>>(X4, (char*)d_out);
}